// round 1
// baseline (speedup 1.0000x reference)
#include <cuda_runtime.h>
#include <math.h>

// Problem constants
#define BB 2048
#define TT 200
#define DD 64
#define H1 80
#define H2 40

#define NTHR 256
#define KPAD 65   // 65 % 32 = 1  -> conflict-free scalar reads
#define A1PAD 81  // 81 % 32 = 17 -> conflict-free
#define A2PAD 41  // 41 % 32 = 9  -> conflict-free

// Shared memory layout (float offsets, all float4-aligned where vector-loaded)
#define OFF_KBUF   0                       // 200*65  = 13000
#define OFF_WEFF   (OFF_KBUF + TT*KPAD)    // 5120 (64x80)
#define OFF_W2     (OFF_WEFF + DD*H1)      // 3200 (80x40)
#define OFF_A1     (OFF_W2   + H1*H2)      // 200*81 = 16200
#define OFF_A2     (OFF_A1   + TT*A1PAD)   // 200*41 = 8200
#define OFF_QS     (OFF_A2   + TT*A2PAD)   // 64
#define OFF_CS     (OFF_QS   + DD)         // 80
#define OFF_WF     (OFF_CS   + H1)         // 40
#define OFF_B2     (OFF_WF   + H2)         // 40
#define OFF_BF     (OFF_B2   + H2)         // 4 (padded)
#define OFF_LBUF   (OFF_BF   + 4)          // 256
#define OFF_RBUF   (OFF_LBUF + NTHR)       // 64
#define OFF_VPART  (OFF_RBUF + 64)         // 256
#define SMEM_FLOATS (OFF_VPART + NTHR)
#define SMEM_BYTES  (SMEM_FLOATS * 4)

// ---- packed f32x2 helpers (sm_100+ only; ptxas never auto-fuses these) ----
__device__ __forceinline__ unsigned long long pack2(float lo, float hi) {
    unsigned long long r;
    asm("mov.b64 %0, {%1, %2};" : "=l"(r) : "r"(__float_as_uint(lo)), "r"(__float_as_uint(hi)));
    return r;
}
__device__ __forceinline__ void unpack2(unsigned long long v, float& lo, float& hi) {
    unsigned int a, b;
    asm("mov.b64 {%0, %1}, %2;" : "=r"(a), "=r"(b) : "l"(v));
    lo = __uint_as_float(a);
    hi = __uint_as_float(b);
}
__device__ __forceinline__ void fma2(unsigned long long& d, unsigned long long a, unsigned long long b) {
    asm("fma.rn.f32x2 %0, %1, %2, %0;" : "+l"(d) : "l"(a), "l"(b));
}

__global__ void __launch_bounds__(NTHR, 1)
din_attention_kernel(const float* __restrict__ q,
                     const float* __restrict__ k,
                     const float* __restrict__ v,
                     const float* __restrict__ W1,
                     const float* __restrict__ b1,
                     const float* __restrict__ a1,
                     const float* __restrict__ W2,
                     const float* __restrict__ b2,
                     const float* __restrict__ a2,
                     const float* __restrict__ Wf,
                     const float* __restrict__ bf,
                     float* __restrict__ out)
{
    extern __shared__ float sm[];
    float* sm_k    = sm + OFF_KBUF;
    float* sm_weff = sm + OFF_WEFF;
    float* sm_w2   = sm + OFF_W2;
    float* sm_a1   = sm + OFF_A1;
    float* sm_a2   = sm + OFF_A2;
    float* sm_q    = sm + OFF_QS;
    float* sm_c    = sm + OFF_CS;
    float* sm_wf   = sm + OFF_WF;
    float* sm_b2   = sm + OFF_B2;
    float* sm_bf   = sm + OFF_BF;
    float* lbuf    = sm + OFF_LBUF;
    float* rbuf    = sm + OFF_RBUF;
    float* vpart   = sm + OFF_VPART;

    const int tid  = threadIdx.x;
    const int b    = blockIdx.x;
    const int lane = tid & 31;
    const int warp = tid >> 5;

    // ---------------- Phase A: stage batch-local + weight data ----------------
    // q row
    if (tid < DD) sm_q[tid] = q[(size_t)b * DD + tid];
    // k tile (coalesced global -> padded smem)
    {
        const float* kb = k + (size_t)b * TT * DD;
        for (int idx = tid; idx < TT * DD; idx += NTHR) {
            int t = idx >> 6, i = idx & 63;
            sm_k[t * KPAD + i] = kb[idx];
        }
    }
    // W2
    for (int idx = tid; idx < H1 * H2; idx += NTHR) sm_w2[idx] = W2[idx];
    // a1 (padded)
    for (int idx = tid; idx < TT * H1; idx += NTHR) {
        int t = idx / H1, j = idx - t * H1;
        sm_a1[t * A1PAD + j] = a1[idx];
    }
    // a2 (padded)
    for (int idx = tid; idx < TT * H2; idx += NTHR) {
        int t = idx / H2, j = idx - t * H2;
        sm_a2[t * A2PAD + j] = a2[idx];
    }
    if (tid < H2) sm_wf[tid] = Wf[tid];
    if (tid >= 32 && tid < 32 + H2) sm_b2[tid - 32] = b2[tid - 32];
    if (tid == 64) sm_bf[0] = bf[0];
    __syncthreads();

    // ---------------- Phase B: per-batch effective weights ----------------
    // Weff[i][j] = (W1b - W1c)[i][j] + q[i]*W1d[i][j]
    for (int idx = tid; idx < DD * H1; idx += NTHR) {
        int i = idx / H1;
        sm_weff[idx] = W1[(DD + i) * H1 + (idx - i * H1)]
                     - W1[(2 * DD + i) * H1 + (idx - i * H1)]
                     + sm_q[i] * W1[(3 * DD + i) * H1 + (idx - i * H1)];
    }
    // c[j] = b1[j] + sum_i q[i]*(W1a + W1c)[i][j]
    if (tid < H1) {
        float c = b1[tid];
        #pragma unroll 8
        for (int i = 0; i < DD; i++)
            c += sm_q[i] * (W1[i * H1 + tid] + W1[(2 * DD + i) * H1 + tid]);
        sm_c[tid] = c;
    }
    __syncthreads();

    // ---------------- Phase C: per-t MLP scorer (packed f32x2) ----------------
    const int t = tid;
    const bool active = (t < TT);
    float logit = 0.f;

    if (active) {
        unsigned long long h[H1 / 2];
        #pragma unroll
        for (int j = 0; j < H1 / 2; j++) h[j] = pack2(sm_c[2 * j], sm_c[2 * j + 1]);

        const float* krow = sm_k + t * KPAD;
        #pragma unroll 2
        for (int i = 0; i < DD; i++) {
            float kv = krow[i];
            unsigned long long kk = pack2(kv, kv);
            const ulonglong2* wrow = reinterpret_cast<const ulonglong2*>(sm_weff + i * H1);
            #pragma unroll
            for (int j4 = 0; j4 < H1 / 4; j4++) {
                ulonglong2 wv = wrow[j4];
                fma2(h[2 * j4],     kk, wv.x);
                fma2(h[2 * j4 + 1], kk, wv.y);
            }
        }

        // PReLU 1
        float h1s[H1];
        const float* a1row = sm_a1 + t * A1PAD;
        #pragma unroll
        for (int j = 0; j < H1 / 2; j++) {
            float lo, hi; unpack2(h[j], lo, hi);
            float al = a1row[2 * j], ah = a1row[2 * j + 1];
            h1s[2 * j]     = (lo > 0.f) ? lo : al * lo;
            h1s[2 * j + 1] = (hi > 0.f) ? hi : ah * hi;
        }

        // Layer 2
        unsigned long long g[H2 / 2];
        #pragma unroll
        for (int j = 0; j < H2 / 2; j++) g[j] = pack2(sm_b2[2 * j], sm_b2[2 * j + 1]);

        #pragma unroll 4
        for (int j1 = 0; j1 < H1; j1++) {
            float hv = h1s[j1];
            unsigned long long hh = pack2(hv, hv);
            const ulonglong2* row = reinterpret_cast<const ulonglong2*>(sm_w2 + j1 * H2);
            #pragma unroll
            for (int j4 = 0; j4 < H2 / 4; j4++) {
                ulonglong2 wv = row[j4];
                fma2(g[2 * j4],     hh, wv.x);
                fma2(g[2 * j4 + 1], hh, wv.y);
            }
        }

        // PReLU 2 + final dot
        logit = sm_bf[0];
        const float* a2row = sm_a2 + t * A2PAD;
        #pragma unroll
        for (int j = 0; j < H2 / 2; j++) {
            float lo, hi; unpack2(g[j], lo, hi);
            float al = a2row[2 * j], ah = a2row[2 * j + 1];
            lo = (lo > 0.f) ? lo : al * lo;
            hi = (hi > 0.f) ? hi : ah * hi;
            logit += lo * sm_wf[2 * j] + hi * sm_wf[2 * j + 1];
        }
    }

    // ---------------- Phase D: softmax over T within the block ----------------
    // block max
    float x = active ? logit : -3.4e38f;
    #pragma unroll
    for (int o = 16; o; o >>= 1) x = fmaxf(x, __shfl_xor_sync(0xffffffffu, x, o));
    if (lane == 0) rbuf[warp] = x;
    __syncthreads();
    if (warp == 0) {
        float y = (lane < 8) ? rbuf[lane] : -3.4e38f;
        #pragma unroll
        for (int o = 4; o; o >>= 1) y = fmaxf(y, __shfl_xor_sync(0xffffffffu, y, o));
        if (lane == 0) rbuf[0] = y;
    }
    __syncthreads();
    const float m = rbuf[0];

    float e = active ? expf(logit - m) : 0.f;
    float s = e;
    #pragma unroll
    for (int o = 16; o; o >>= 1) s += __shfl_xor_sync(0xffffffffu, s, o);
    if (lane == 0) rbuf[8 + warp] = s;
    __syncthreads();
    if (warp == 0) {
        float y = (lane < 8) ? rbuf[8 + lane] : 0.f;
        #pragma unroll
        for (int o = 4; o; o >>= 1) y += __shfl_xor_sync(0xffffffffu, y, o);
        if (lane == 0) rbuf[8] = y;
    }
    __syncthreads();
    const float inv = 1.f / rbuf[8];
    if (active) lbuf[t] = e * inv;
    __syncthreads();

    // ---------------- Phase E: out[b][d] = sum_t w[t] * v[b][t][d] ----------------
    {
        const int d = tid & 63;
        const int gidx = tid >> 6;  // 0..3
        const float* vb = v + (size_t)b * TT * DD;
        float acc = 0.f;
        for (int t2 = gidx; t2 < TT; t2 += 4)
            acc += lbuf[t2] * vb[t2 * DD + d];
        vpart[tid] = acc;
    }
    __syncthreads();
    if (tid < DD) {
        out[(size_t)b * DD + tid] =
            vpart[tid] + vpart[64 + tid] + vpart[128 + tid] + vpart[192 + tid];
    }
}

extern "C" void kernel_launch(void* const* d_in, const int* in_sizes, int n_in,
                              void* d_out, int out_size)
{
    const float* q  = (const float*)d_in[0];
    const float* k  = (const float*)d_in[1];
    const float* v  = (const float*)d_in[2];
    const float* W1 = (const float*)d_in[3];
    const float* b1 = (const float*)d_in[4];
    const float* a1 = (const float*)d_in[5];
    const float* W2 = (const float*)d_in[6];
    const float* b2 = (const float*)d_in[7];
    const float* a2 = (const float*)d_in[8];
    const float* Wf = (const float*)d_in[9];
    const float* bf = (const float*)d_in[10];
    float* out = (float*)d_out;

    cudaFuncSetAttribute(din_attention_kernel,
                         cudaFuncAttributeMaxDynamicSharedMemorySize, SMEM_BYTES);
    din_attention_kernel<<<BB, NTHR, SMEM_BYTES>>>(q, k, v, W1, b1, a1, W2, b2, a2, Wf, bf, out);
}

// round 2
// speedup vs baseline: 1.1046x; 1.1046x over previous
#include <cuda_runtime.h>
#include <math.h>

// Problem constants
#define BB 2048
#define TT 200
#define DD 64
#define H1 80
#define H2 40
#define H1H 40   // per-thread half of H1

#define NTHR 512
#define KPAD 65   // stride 65: (t*65+i)%32 distinct across rows -> conflict-free

// Shared memory layout (float offsets)
#define OFF_KBUF   0                        // 200*65 = 13000
#define OFF_WEFF   (OFF_KBUF + TT*KPAD)     // 64*80 = 5120 (16B aligned: 13000*4%16==0)
#define OFF_W2     (OFF_WEFF + DD*H1)       // 80*40 = 3200
#define OFF_QS     (OFF_W2   + H1*H2)       // 64
#define OFF_CS     (OFF_QS   + DD)          // 80
#define OFF_WF     (OFF_CS   + H1)          // 40
#define OFF_B2     (OFF_WF   + H2)          // 40
#define OFF_BF     (OFF_B2   + H2)          // 8
#define OFF_LBUF   (OFF_BF   + 8)           // 256
#define OFF_RBUF   (OFF_LBUF + 256)         // 32
#define OFF_VPART  (OFF_RBUF + 32)          // 512
#define SMEM_FLOATS (OFF_VPART + NTHR)
#define SMEM_BYTES  (SMEM_FLOATS * 4)

typedef unsigned long long ull;

// ---- packed f32x2 helpers (sm_100+; ptxas never auto-fuses) ----
__device__ __forceinline__ ull pack2(float lo, float hi) {
    ull r;
    asm("mov.b64 %0, {%1, %2};" : "=l"(r) : "r"(__float_as_uint(lo)), "r"(__float_as_uint(hi)));
    return r;
}
__device__ __forceinline__ void unpack2(ull v, float& lo, float& hi) {
    unsigned int a, b;
    asm("mov.b64 {%0, %1}, %2;" : "=r"(a), "=r"(b) : "l"(v));
    lo = __uint_as_float(a);
    hi = __uint_as_float(b);
}
__device__ __forceinline__ void fma2(ull& d, ull a, ull b) {
    asm("fma.rn.f32x2 %0, %1, %2, %0;" : "+l"(d) : "l"(a), "l"(b));
}

__global__ void __launch_bounds__(NTHR, 1)
din_attention_kernel(const float* __restrict__ q,
                     const float* __restrict__ k,
                     const float* __restrict__ v,
                     const float* __restrict__ W1,
                     const float* __restrict__ b1,
                     const float* __restrict__ a1,
                     const float* __restrict__ W2,
                     const float* __restrict__ b2,
                     const float* __restrict__ a2,
                     const float* __restrict__ Wf,
                     const float* __restrict__ bf,
                     float* __restrict__ out)
{
    extern __shared__ float sm[];
    float* sm_k    = sm + OFF_KBUF;
    float* sm_weff = sm + OFF_WEFF;
    float* sm_w2   = sm + OFF_W2;
    float* sm_q    = sm + OFF_QS;
    float* sm_c    = sm + OFF_CS;
    float* sm_wf   = sm + OFF_WF;
    float* sm_b2   = sm + OFF_B2;
    float* sm_bf   = sm + OFF_BF;
    float* lbuf    = sm + OFF_LBUF;
    float* rbuf    = sm + OFF_RBUF;
    float* vpart   = sm + OFF_VPART;

    const int tid  = threadIdx.x;
    const int b    = blockIdx.x;
    const int lane = tid & 31;
    const int warp = tid >> 5;

    // ---------------- Phase A: stage batch-local + weight data ----------------
    if (tid < DD) sm_q[tid] = q[(size_t)b * DD + tid];
    {
        // k tile: coalesced float4 loads, scalar stores into padded smem
        const float4* kb4 = reinterpret_cast<const float4*>(k + (size_t)b * TT * DD);
        for (int x = tid; x < TT * DD / 4; x += NTHR) {
            float4 vv = kb4[x];
            int t = x >> 4;            // 16 float4 per row
            int i = (x & 15) * 4;
            float* dst = sm_k + t * KPAD + i;
            dst[0] = vv.x; dst[1] = vv.y; dst[2] = vv.z; dst[3] = vv.w;
        }
    }
    for (int idx = tid; idx < H1 * H2; idx += NTHR) sm_w2[idx] = W2[idx];
    if (tid < H2) sm_wf[tid] = Wf[tid];
    if (tid >= 64 && tid < 64 + H2) sm_b2[tid - 64] = b2[tid - 64];
    if (tid == 128) sm_bf[0] = bf[0];
    __syncthreads();

    // ---------------- Phase B: per-batch effective weights ----------------
    // Weff[i][j] = (W1b - W1c)[i][j] + q[i]*W1d[i][j]
    for (int idx = tid; idx < DD * H1; idx += NTHR) {
        int i = idx / H1;
        int j = idx - i * H1;
        sm_weff[idx] = W1[(DD + i) * H1 + j]
                     - W1[(2 * DD + i) * H1 + j]
                     + sm_q[i] * W1[(3 * DD + i) * H1 + j];
    }
    // c[j] = b1[j] + sum_i q[i]*(W1a + W1c)[i][j]
    if (tid < H1) {
        float c = b1[tid];
        #pragma unroll 8
        for (int i = 0; i < DD; i++)
            c += sm_q[i] * (W1[i * H1 + tid] + W1[(2 * DD + i) * H1 + tid]);
        sm_c[tid] = c;
    }
    __syncthreads();

    // ---------------- Phase C: per-t MLP scorer, 2 threads per t ----------------
    const int t    = tid >> 1;
    const int half = tid & 1;
    const int tc   = (t < TT) ? t : (TT - 1);   // clamp; extra threads compute dupes

    // prefetch a1 half-row (independent of layer-1 compute; covered by scoreboard)
    float4 a1r[10];
    {
        const float4* a1p = reinterpret_cast<const float4*>(a1 + tc * H1 + half * H1H);
        #pragma unroll
        for (int j = 0; j < 10; j++) a1r[j] = __ldg(a1p + j);
    }

    // Layer 1: this thread's 40 of 80 outputs
    ull h[H1H / 2];
    {
        const float* cc = sm_c + half * H1H;
        #pragma unroll
        for (int j = 0; j < H1H / 2; j++) h[j] = pack2(cc[2 * j], cc[2 * j + 1]);

        const float* krow = sm_k + tc * KPAD;
        #pragma unroll 4
        for (int i = 0; i < DD; i++) {
            float kv = krow[i];
            ull kk = pack2(kv, kv);
            const ulonglong2* wrow =
                reinterpret_cast<const ulonglong2*>(sm_weff + i * H1 + half * H1H);
            #pragma unroll
            for (int j4 = 0; j4 < H1H / 4; j4++) {
                ulonglong2 wv = wrow[j4];
                fma2(h[2 * j4],     kk, wv.x);
                fma2(h[2 * j4 + 1], kk, wv.y);
            }
        }
    }

    // PReLU 1
    float h1s[H1H];
    #pragma unroll
    for (int j = 0; j < H1H / 2; j++) {
        float lo, hi; unpack2(h[j], lo, hi);
        float4 av = a1r[j >> 1];
        float al = (j & 1) ? av.z : av.x;
        float ah = (j & 1) ? av.w : av.y;
        h1s[2 * j]     = (lo > 0.f) ? lo : al * lo;
        h1s[2 * j + 1] = (hi > 0.f) ? hi : ah * hi;
    }

    // Layer 2: partial over this thread's 40 H1 inputs, all 40 outputs
    ull g[H2 / 2];
    #pragma unroll
    for (int j = 0; j < H2 / 2; j++)
        g[j] = (half == 0) ? pack2(sm_b2[2 * j], sm_b2[2 * j + 1]) : pack2(0.f, 0.f);

    const int j1base = half * H1H;
    float4 a2r[10];

    #pragma unroll 4
    for (int j1 = 0; j1 < 24; j1++) {
        float hv = h1s[j1];
        ull hh = pack2(hv, hv);
        const ulonglong2* row =
            reinterpret_cast<const ulonglong2*>(sm_w2 + (j1base + j1) * H2);
        #pragma unroll
        for (int j4 = 0; j4 < H2 / 4; j4++) {
            ulonglong2 wv = row[j4];
            fma2(g[2 * j4],     hh, wv.x);
            fma2(g[2 * j4 + 1], hh, wv.y);
        }
    }
    // prefetch a2 row here (latency covered by remaining 16 iterations)
    {
        const float4* a2p = reinterpret_cast<const float4*>(a2 + tc * H2);
        #pragma unroll
        for (int j = 0; j < 10; j++) a2r[j] = __ldg(a2p + j);
    }
    #pragma unroll 4
    for (int j1 = 24; j1 < H1H; j1++) {
        float hv = h1s[j1];
        ull hh = pack2(hv, hv);
        const ulonglong2* row =
            reinterpret_cast<const ulonglong2*>(sm_w2 + (j1base + j1) * H2);
        #pragma unroll
        for (int j4 = 0; j4 < H2 / 4; j4++) {
            ulonglong2 wv = row[j4];
            fma2(g[2 * j4],     hh, wv.x);
            fma2(g[2 * j4 + 1], hh, wv.y);
        }
    }

    // Combine the two halves' partials via lane-pair butterfly
    float gv[H2];
    #pragma unroll
    for (int j = 0; j < H2 / 2; j++) {
        float lo, hi; unpack2(g[j], lo, hi);
        gv[2 * j] = lo; gv[2 * j + 1] = hi;
    }
    #pragma unroll
    for (int j = 0; j < H2; j++)
        gv[j] += __shfl_xor_sync(0xffffffffu, gv[j], 1);

    // PReLU 2 + final dot (both lanes of a pair compute the same logit)
    float logit = sm_bf[0];
    #pragma unroll
    for (int j4 = 0; j4 < 10; j4++) {
        float4 av = a2r[j4];
        float x0 = gv[4 * j4 + 0], x1 = gv[4 * j4 + 1];
        float x2 = gv[4 * j4 + 2], x3 = gv[4 * j4 + 3];
        x0 = (x0 > 0.f) ? x0 : av.x * x0;
        x1 = (x1 > 0.f) ? x1 : av.y * x1;
        x2 = (x2 > 0.f) ? x2 : av.z * x2;
        x3 = (x3 > 0.f) ? x3 : av.w * x3;
        logit += x0 * sm_wf[4 * j4 + 0] + x1 * sm_wf[4 * j4 + 1]
               + x2 * sm_wf[4 * j4 + 2] + x3 * sm_wf[4 * j4 + 3];
    }

    // ---------------- Phase D: softmax over T within the block ----------------
    const bool valid = (t < TT);
    float x = valid ? logit : -3.4e38f;
    #pragma unroll
    for (int o = 16; o; o >>= 1) x = fmaxf(x, __shfl_xor_sync(0xffffffffu, x, o));
    if (lane == 0) rbuf[warp] = x;
    __syncthreads();
    if (warp == 0) {
        float y = (lane < 16) ? rbuf[lane] : -3.4e38f;
        #pragma unroll
        for (int o = 8; o; o >>= 1) y = fmaxf(y, __shfl_xor_sync(0xffffffffu, y, o));
        if (lane == 0) rbuf[0] = y;
    }
    __syncthreads();
    const float m = rbuf[0];

    float e = (valid && half == 0) ? __expf(logit - m) : 0.f;
    float s = e;
    #pragma unroll
    for (int o = 16; o; o >>= 1) s += __shfl_xor_sync(0xffffffffu, s, o);
    if (lane == 0) rbuf[16 + warp] = s;
    __syncthreads();
    if (warp == 0) {
        float y = (lane < 16) ? rbuf[16 + lane] : 0.f;
        #pragma unroll
        for (int o = 8; o; o >>= 1) y += __shfl_xor_sync(0xffffffffu, y, o);
        if (lane == 0) rbuf[16] = y;
    }
    __syncthreads();
    const float inv = 1.f / rbuf[16];
    if (valid && half == 0) lbuf[t] = e * inv;
    __syncthreads();

    // ---------------- Phase E: out[b][d] = sum_t w[t] * v[b][t][d] ----------------
    {
        const int d   = tid & 63;
        const int grp = tid >> 6;   // 0..7
        const float* vb = v + (size_t)b * TT * DD;
        float acc = 0.f;
        for (int t2 = grp; t2 < TT; t2 += 8)
            acc += lbuf[t2] * vb[t2 * DD + d];
        vpart[tid] = acc;
    }
    __syncthreads();
    if (tid < DD) {
        float r = 0.f;
        #pragma unroll
        for (int g2 = 0; g2 < 8; g2++) r += vpart[g2 * 64 + tid];
        out[(size_t)b * DD + tid] = r;
    }
}

extern "C" void kernel_launch(void* const* d_in, const int* in_sizes, int n_in,
                              void* d_out, int out_size)
{
    const float* q  = (const float*)d_in[0];
    const float* k  = (const float*)d_in[1];
    const float* v  = (const float*)d_in[2];
    const float* W1 = (const float*)d_in[3];
    const float* b1 = (const float*)d_in[4];
    const float* a1 = (const float*)d_in[5];
    const float* W2 = (const float*)d_in[6];
    const float* b2 = (const float*)d_in[7];
    const float* a2 = (const float*)d_in[8];
    const float* Wf = (const float*)d_in[9];
    const float* bf = (const float*)d_in[10];
    float* out = (float*)d_out;

    cudaFuncSetAttribute(din_attention_kernel,
                         cudaFuncAttributeMaxDynamicSharedMemorySize, SMEM_BYTES);
    din_attention_kernel<<<BB, NTHR, SMEM_BYTES>>>(q, k, v, W1, b1, a1, W2, b2, a2, Wf, bf, out);
}

// round 3
// speedup vs baseline: 1.5281x; 1.3835x over previous
#include <cuda_runtime.h>
#include <math.h>

// Problem constants
#define BB 2048
#define TT 200
#define DD 64
#define H1 80
#define H2 40

#define NTHR 512
#define KPAD 65    // k rows: bank = (65t+i)%32 = (t+i)%32 -> conflict-free
#define WES  646   // weff per-js stride: 646%32=6 -> 8 distinct bank-pairs; even -> 8B aligned
#define H1TS 200   // h1T row stride (floats): 200%32=8; tg offsets {0,4,8,12} -> conflict-free

// Shared memory layout (float offsets)
#define OFF_KBUF  0                  // 200*65 = 13000
#define OFF_WEFF  13000              // 8*646 = 5168  -> ends 18168
#define OFF_H1T   0                  // 80*200 = 16000 (ALIASES kbuf+weff; used strictly after)
#define OFF_W2    18168              // 80*40 = 3200
#define OFF_Q     21368              // 64
#define OFF_C     21432              // 80
#define OFF_WF    21512              // 40
#define OFF_B2    21552              // 40
#define OFF_BF    21592              // 8
#define OFF_LBUF  21600              // 208
#define OFF_RBUF  21808              // 48
#define OFF_VPART 21856              // 512
#define SMEM_FLOATS 22368
#define SMEM_BYTES  (SMEM_FLOATS * 4)

typedef unsigned long long ull;

// ---- packed f32x2 helpers (sm_100+; ptxas never auto-fuses) ----
__device__ __forceinline__ ull pack2(float lo, float hi) {
    ull r;
    asm("mov.b64 %0, {%1, %2};" : "=l"(r) : "r"(__float_as_uint(lo)), "r"(__float_as_uint(hi)));
    return r;
}
__device__ __forceinline__ void unpack2(ull v, float& lo, float& hi) {
    unsigned int a, b;
    asm("mov.b64 {%0, %1}, %2;" : "=r"(a), "=r"(b) : "l"(v));
    lo = __uint_as_float(a);
    hi = __uint_as_float(b);
}
__device__ __forceinline__ void fma2(ull& d, ull a, ull b) {
    asm("fma.rn.f32x2 %0, %1, %2, %0;" : "+l"(d) : "l"(a), "l"(b));
}

__global__ void __launch_bounds__(NTHR, 1)
din_attention_kernel(const float* __restrict__ q,
                     const float* __restrict__ k,
                     const float* __restrict__ v,
                     const float* __restrict__ W1,
                     const float* __restrict__ b1,
                     const float* __restrict__ a1,
                     const float* __restrict__ W2,
                     const float* __restrict__ b2,
                     const float* __restrict__ a2,
                     const float* __restrict__ Wf,
                     const float* __restrict__ bf,
                     float* __restrict__ out)
{
    extern __shared__ float sm[];
    float* lbuf  = sm + OFF_LBUF;
    float* rbuf  = sm + OFF_RBUF;
    float* vpart = sm + OFF_VPART;

    const int tid  = threadIdx.x;
    const int b    = blockIdx.x;
    const int lane = tid & 31;
    const int warp = tid >> 5;

    const int TG  = tid >> 3;            // t-group 0..63
    const int JS  = tid & 7;             // column slot 0..7
    const int TGC = (TG < TT / 4) ? TG : (TT / 4 - 1);  // clamp dups
    const int t0  = 4 * TGC;

    // ---------------- Phase A: stage batch-local + weight data ----------------
    if (tid < DD) sm[OFF_Q + tid] = q[(size_t)b * DD + tid];
    {
        const float4* kb4 = reinterpret_cast<const float4*>(k + (size_t)b * TT * DD);
        for (int x = tid; x < TT * DD / 4; x += NTHR) {
            float4 vv = kb4[x];
            int t = x >> 4;            // 16 float4 per row
            int i = (x & 15) * 4;
            float* dst = sm + OFF_KBUF + t * KPAD + i;
            dst[0] = vv.x; dst[1] = vv.y; dst[2] = vv.z; dst[3] = vv.w;
        }
    }
    for (int idx = tid; idx < H1 * H2; idx += NTHR) sm[OFF_W2 + idx] = W2[idx];
    if (tid < H2) sm[OFF_WF + tid] = Wf[tid];
    if (tid >= 64 && tid < 64 + H2) sm[OFF_B2 + tid - 64] = b2[tid - 64];
    if (tid == 128) sm[OFF_BF] = bf[0];
    __syncthreads();

    // ---------------- Phase B: per-batch effective weights ----------------
    // weff_r[js][i][10]: Weff[i][j] = (W1b - W1c)[i][j] + q[i]*W1d[i][j]
    for (int idx = tid; idx < DD * H1; idx += NTHR) {
        int i = idx / H1;
        int j = idx - i * H1;
        float w = W1[(DD + i) * H1 + j]
                - W1[(2 * DD + i) * H1 + j]
                + sm[OFF_Q + i] * W1[(3 * DD + i) * H1 + j];
        sm[OFF_WEFF + (j / 10) * WES + i * 10 + (j % 10)] = w;
    }
    // c[j] = b1[j] + sum_i q[i]*(W1a + W1c)[i][j]
    if (tid < H1) {
        float c = b1[tid];
        #pragma unroll 8
        for (int i = 0; i < DD; i++)
            c += sm[OFF_Q + i] * (W1[i * H1 + tid] + W1[(2 * DD + i) * H1 + tid]);
        sm[OFF_C + tid] = c;
    }
    __syncthreads();

    // ---------------- Phase C: layer 1, 4t x 10j register tile ----------------
    ull h[20];  // h[tt*5 + jp], packed over adjacent j
    {
        const ull* cp = reinterpret_cast<const ull*>(sm + OFF_C + 10 * JS);
        #pragma unroll
        for (int jp = 0; jp < 5; jp++) {
            ull cc = cp[jp];
            h[jp] = cc; h[5 + jp] = cc; h[10 + jp] = cc; h[15 + jp] = cc;
        }
    }
    {
        const float* kb = sm + OFF_KBUF + t0 * KPAD;
        const float* wb = sm + OFF_WEFF + JS * WES;
        #pragma unroll 2
        for (int i = 0; i < DD; i++) {
            float k0 = kb[i];
            float k1 = kb[KPAD + i];
            float k2 = kb[2 * KPAD + i];
            float k3 = kb[3 * KPAD + i];
            ull kk0 = pack2(k0, k0), kk1 = pack2(k1, k1);
            ull kk2 = pack2(k2, k2), kk3 = pack2(k3, k3);
            const ull* wp = reinterpret_cast<const ull*>(wb + i * 10);
            #pragma unroll
            for (int jp = 0; jp < 5; jp++) {
                ull wv = wp[jp];
                fma2(h[jp],      kk0, wv);
                fma2(h[5 + jp],  kk1, wv);
                fma2(h[10 + jp], kk2, wv);
                fma2(h[15 + jp], kk3, wv);
            }
        }
    }

    // PReLU 1 (alpha from L2 via __ldg)
    float h1v[4][10];
    {
        float2 a1r[4][5];
        #pragma unroll
        for (int tt = 0; tt < 4; tt++) {
            const float2* ap = reinterpret_cast<const float2*>(a1 + (t0 + tt) * H1 + 10 * JS);
            #pragma unroll
            for (int jp = 0; jp < 5; jp++) a1r[tt][jp] = __ldg(ap + jp);
        }
        #pragma unroll
        for (int tt = 0; tt < 4; tt++) {
            #pragma unroll
            for (int jp = 0; jp < 5; jp++) {
                float lo, hi; unpack2(h[tt * 5 + jp], lo, hi);
                float2 av = a1r[tt][jp];
                h1v[tt][2 * jp]     = (lo > 0.f) ? lo : av.x * lo;
                h1v[tt][2 * jp + 1] = (hi > 0.f) ? hi : av.y * hi;
            }
        }
    }

    __syncthreads();   // kbuf + weff dead; safe to overwrite with h1T
    {
        float* hb = sm + OFF_H1T;
        #pragma unroll
        for (int jj = 0; jj < 10; jj++) {
            float4 vv = make_float4(h1v[0][jj], h1v[1][jj], h1v[2][jj], h1v[3][jj]);
            *reinterpret_cast<float4*>(hb + (10 * JS + jj) * H1TS + 4 * TGC) = vv;
        }
    }
    __syncthreads();

    // ---------------- Phase D: layer 2, 4t x 5j2 register tile ----------------
    ull g0[5], g1[5];  // packed over t-pairs (t0,t1) and (t2,t3)
    {
        const float* b2p = sm + OFF_B2 + 5 * JS;
        #pragma unroll
        for (int c = 0; c < 5; c++) {
            ull bb = pack2(b2p[c], b2p[c]);
            g0[c] = bb; g1[c] = bb;
        }
    }
    {
        const float* hb2 = sm + OFF_H1T + 4 * TGC;
        const float* w2b = sm + OFF_W2 + 5 * JS;
        #pragma unroll 2
        for (int j1 = 0; j1 < H1; j1++) {
            const ull* hp = reinterpret_cast<const ull*>(hb2 + j1 * H1TS);
            ull h01 = hp[0], h23 = hp[1];
            const float* wp = w2b + j1 * H2;
            #pragma unroll
            for (int c = 0; c < 5; c++) {
                ull ww = pack2(wp[c], wp[c]);
                fma2(g0[c], h01, ww);
                fma2(g1[c], h23, ww);
            }
        }
    }

    // PReLU 2 + final dot; partial logits per js, reduce over 8 lanes
    float lg0, lg1, lg2, lg3;
    {
        float bfv = (JS == 0) ? sm[OFF_BF] : 0.f;
        lg0 = bfv; lg1 = bfv; lg2 = bfv; lg3 = bfv;
        const float* a2b = a2 + 5 * JS;
        #pragma unroll
        for (int c = 0; c < 5; c++) {
            float w  = sm[OFF_WF + 5 * JS + c];
            float p0 = __ldg(a2b + (t0 + 0) * H2 + c);
            float p1 = __ldg(a2b + (t0 + 1) * H2 + c);
            float p2 = __ldg(a2b + (t0 + 2) * H2 + c);
            float p3 = __ldg(a2b + (t0 + 3) * H2 + c);
            float x0, x1; unpack2(g0[c], x0, x1);
            float x2, x3; unpack2(g1[c], x2, x3);
            x0 = (x0 > 0.f) ? x0 : p0 * x0;
            x1 = (x1 > 0.f) ? x1 : p1 * x1;
            x2 = (x2 > 0.f) ? x2 : p2 * x2;
            x3 = (x3 > 0.f) ? x3 : p3 * x3;
            lg0 += x0 * w; lg1 += x1 * w; lg2 += x2 * w; lg3 += x3 * w;
        }
        #pragma unroll
        for (int o = 1; o < 8; o <<= 1) {
            lg0 += __shfl_xor_sync(0xffffffffu, lg0, o);
            lg1 += __shfl_xor_sync(0xffffffffu, lg1, o);
            lg2 += __shfl_xor_sync(0xffffffffu, lg2, o);
            lg3 += __shfl_xor_sync(0xffffffffu, lg3, o);
        }
        if (JS == 0)
            *reinterpret_cast<float4*>(lbuf + 4 * TGC) = make_float4(lg0, lg1, lg2, lg3);
    }
    __syncthreads();

    // ---------------- Phase E: softmax over T within the block ----------------
    const bool valid = (tid < TT);
    float logit = valid ? lbuf[tid] : -3.4e38f;
    float x = logit;
    #pragma unroll
    for (int o = 16; o; o >>= 1) x = fmaxf(x, __shfl_xor_sync(0xffffffffu, x, o));
    if (lane == 0) rbuf[warp] = x;
    __syncthreads();
    if (warp == 0) {
        float y = (lane < 16) ? rbuf[lane] : -3.4e38f;
        #pragma unroll
        for (int o = 8; o; o >>= 1) y = fmaxf(y, __shfl_xor_sync(0xffffffffu, y, o));
        if (lane == 0) rbuf[0] = y;
    }
    __syncthreads();
    const float m = rbuf[0];

    float e = valid ? __expf(logit - m) : 0.f;
    float s = e;
    #pragma unroll
    for (int o = 16; o; o >>= 1) s += __shfl_xor_sync(0xffffffffu, s, o);
    if (lane == 0) rbuf[16 + warp] = s;
    __syncthreads();
    if (warp == 0) {
        float y = (lane < 16) ? rbuf[16 + lane] : 0.f;
        #pragma unroll
        for (int o = 8; o; o >>= 1) y += __shfl_xor_sync(0xffffffffu, y, o);
        if (lane == 0) rbuf[16] = y;
    }
    __syncthreads();
    const float inv = 1.f / rbuf[16];
    if (valid) lbuf[tid] = e * inv;
    __syncthreads();

    // ---------------- Phase F: out[b][d] = sum_t w[t] * v[b][t][d] ----------------
    {
        const int d   = tid & 63;
        const int grp = tid >> 6;   // 0..7
        const float* vb = v + (size_t)b * TT * DD;
        float acc = 0.f;
        for (int t2 = grp; t2 < TT; t2 += 8)
            acc += lbuf[t2] * vb[t2 * DD + d];
        vpart[tid] = acc;
    }
    __syncthreads();
    if (tid < DD) {
        float r = 0.f;
        #pragma unroll
        for (int g2 = 0; g2 < 8; g2++) r += vpart[g2 * 64 + tid];
        out[(size_t)b * DD + tid] = r;
    }
}

extern "C" void kernel_launch(void* const* d_in, const int* in_sizes, int n_in,
                              void* d_out, int out_size)
{
    const float* q  = (const float*)d_in[0];
    const float* k  = (const float*)d_in[1];
    const float* v  = (const float*)d_in[2];
    const float* W1 = (const float*)d_in[3];
    const float* b1 = (const float*)d_in[4];
    const float* a1 = (const float*)d_in[5];
    const float* W2 = (const float*)d_in[6];
    const float* b2 = (const float*)d_in[7];
    const float* a2 = (const float*)d_in[8];
    const float* Wf = (const float*)d_in[9];
    const float* bf = (const float*)d_in[10];
    float* out = (float*)d_out;

    cudaFuncSetAttribute(din_attention_kernel,
                         cudaFuncAttributeMaxDynamicSharedMemorySize, SMEM_BYTES);
    din_attention_kernel<<<BB, NTHR, SMEM_BYTES>>>(q, k, v, W1, b1, a1, W2, b2, a2, Wf, bf, out);
}